// round 3
// baseline (speedup 1.0000x reference)
#include <cuda_runtime.h>
#include <cstdint>

#define N_NODES 100000
#define D 128
#define N_EDGES 1600000
#define TILE_ROWS 64

// Scratch (allocation-free rule: __device__ globals)
__device__ float g_neigh[(size_t)N_NODES * D];   // 51.2 MB
__device__ float g_deg[N_NODES];
__device__ int   g_is64;

// ---------------- helpers: packed f32x2 ----------------
__device__ __forceinline__ unsigned long long fma2(unsigned long long a,
                                                   unsigned long long b,
                                                   unsigned long long c) {
    unsigned long long d;
    asm("fma.rn.f32x2 %0, %1, %2, %3;" : "=l"(d) : "l"(a), "l"(b), "l"(c));
    return d;
}
__device__ __forceinline__ unsigned long long dup2(float a) {
    unsigned long long d;
    asm("mov.b64 %0, {%1, %1};" : "=l"(d) : "f"(a));
    return d;
}
__device__ __forceinline__ float2 unpack2(unsigned long long v) {
    float2 r;
    asm("mov.b64 {%0, %1}, %2;" : "=f"(r.x), "=f"(r.y) : "l"(v));
    return r;
}

// ---------------- kernel 0: index dtype sniff ----------------
// int64 data: 64 consecutive int64 reads all land in [0, N_NODES).
// int32 data: an int64 read = lo | (hi<<32); hi is a random index,
// nonzero w.p. ~1 per element -> out of range within 64 samples.
__global__ void sniff_kernel(const void* __restrict__ src) {
    if (threadIdx.x == 0 && blockIdx.x == 0) {
        const long long* p = (const long long*)src;
        int ok = 1;
        #pragma unroll 1
        for (int i = 0; i < 64; i++) {
            long long v = p[i];
            if (v < 0 || v >= N_NODES) { ok = 0; break; }
        }
        g_is64 = ok;
    }
}

// ---------------- kernel 1: zero scratch ----------------
__global__ void zero_kernel() {
    size_t idx = (size_t)blockIdx.x * blockDim.x + threadIdx.x;
    size_t stride = (size_t)gridDim.x * blockDim.x;
    const size_t total4 = (size_t)N_NODES * D / 4;  // 3.2M float4
    float4 z = make_float4(0.f, 0.f, 0.f, 0.f);
    for (size_t i = idx; i < total4; i += stride)
        reinterpret_cast<float4*>(g_neigh)[i] = z;
    for (size_t i = idx; i < N_NODES / 4; i += stride)
        reinterpret_cast<float4*>(g_deg)[i] = z;
}

// ---------------- kernel 2: edge scatter (warp per edge) ----------------
__global__ void edge_kernel(const float* __restrict__ h,
                            const void* __restrict__ src_raw,
                            const void* __restrict__ dst_raw) {
    const int is64 = g_is64;
    const int* __restrict__ src32 = (const int*)src_raw;
    const int* __restrict__ dst32 = (const int*)dst_raw;
    const long long* __restrict__ src64 = (const long long*)src_raw;
    const long long* __restrict__ dst64 = (const long long*)dst_raw;

    int lane = threadIdx.x & 31;
    int warp = (int)((blockIdx.x * blockDim.x + threadIdx.x) >> 5);
    int nwarps = (int)((gridDim.x * blockDim.x) >> 5);
    for (int e = warp; e < N_EDGES; e += nwarps) {
        int s, d;
        if (is64) { s = (int)src64[e]; d = (int)dst64[e]; }
        else      { s = src32[e];      d = dst32[e]; }
        if ((unsigned)s >= N_NODES || (unsigned)d >= N_NODES) continue;

        float4 v = reinterpret_cast<const float4*>(h + (size_t)s * D)[lane];
        float4* p = reinterpret_cast<float4*>(g_neigh + (size_t)d * D) + lane;
        atomicAdd(p, v);   // vector atomic, cc >= 9.0
        if (lane == 0) atomicAdd(&g_deg[d], 1.0f);
    }
}

// ---------------- kernel 3: fused mean + dual GEMM ----------------
// out[n, c] = sum_k h[n,k] Wself[k,c] + (neigh[n,k]/max(deg,1)) Wneigh[k,c]
// Block: 512 threads, tile = 64 rows x 128 cols. Thread = 4 rows x 4 cols.
// SMEM: Wself[128x128] + Wneigh[128x128] + Xs[64x128] + Xn[64x128] = 192 KB.
__global__ __launch_bounds__(512, 1)
void out_kernel(const float* __restrict__ h,
                const float* __restrict__ Wself,
                const float* __restrict__ Wneigh,
                float* __restrict__ out) {
    extern __shared__ float smem[];
    float* sWs = smem;                      // 16384
    float* sWn = sWs + 16384;               // 16384
    float* sXs = sWn + 16384;               // 64*128
    float* sXn = sXs + TILE_ROWS * D;       // 64*128

    int tid = threadIdx.x;

    // Load both weight matrices once per block (persistent blocks).
    for (int i = tid; i < 16384 / 4; i += 512) {
        reinterpret_cast<float4*>(sWs)[i] = reinterpret_cast<const float4*>(Wself)[i];
        reinterpret_cast<float4*>(sWn)[i] = reinterpret_cast<const float4*>(Wneigh)[i];
    }

    int cg = tid & 31;   // column group: cols [cg*4, cg*4+4)
    int rg = tid >> 5;   // row group:    rows [rg*4, rg*4+4)
    int c0 = cg * 4;
    int r0 = rg * 4;

    const int ntiles = (N_NODES + TILE_ROWS - 1) / TILE_ROWS;

    for (int tile = blockIdx.x; tile < ntiles; tile += gridDim.x) {
        int rowbase = tile * TILE_ROWS;
        __syncthreads();  // protect smem (also covers W-load on first tile)

        // cooperative tile load: 64 rows x 32 float4 = 2048 float4, 4 per thread
        #pragma unroll
        for (int j = 0; j < 4; j++) {
            int idx = tid + 512 * j;
            int r = idx >> 5;
            int c4 = idx & 31;
            int row = rowbase + r;
            if (row < N_NODES) {
                float4 a = reinterpret_cast<const float4*>(h + (size_t)row * D)[c4];
                reinterpret_cast<float4*>(sXs + r * D)[c4] = a;
                float inv = 1.0f / fmaxf(g_deg[row], 1.0f);
                float4 b = reinterpret_cast<const float4*>(g_neigh + (size_t)row * D)[c4];
                b.x *= inv; b.y *= inv; b.z *= inv; b.w *= inv;
                reinterpret_cast<float4*>(sXn + r * D)[c4] = b;
            }
        }
        __syncthreads();

        unsigned long long acc[4][2];
        #pragma unroll
        for (int i = 0; i < 4; i++) { acc[i][0] = 0ull; acc[i][1] = 0ull; }

        #pragma unroll 4
        for (int kk = 0; kk < D; kk += 4) {
            float4 as[4], an[4];
            #pragma unroll
            for (int i = 0; i < 4; i++) {
                as[i] = *reinterpret_cast<const float4*>(sXs + (r0 + i) * D + kk);
                an[i] = *reinterpret_cast<const float4*>(sXn + (r0 + i) * D + kk);
            }
            #pragma unroll
            for (int dk = 0; dk < 4; dk++) {
                ulonglong2 w2s = *reinterpret_cast<const ulonglong2*>(sWs + (kk + dk) * D + c0);
                ulonglong2 w2n = *reinterpret_cast<const ulonglong2*>(sWn + (kk + dk) * D + c0);
                #pragma unroll
                for (int i = 0; i < 4; i++) {
                    float a_s = reinterpret_cast<const float*>(&as[i])[dk];
                    float a_n = reinterpret_cast<const float*>(&an[i])[dk];
                    unsigned long long a2s = dup2(a_s);
                    unsigned long long a2n = dup2(a_n);
                    acc[i][0] = fma2(a2s, w2s.x, acc[i][0]);
                    acc[i][1] = fma2(a2s, w2s.y, acc[i][1]);
                    acc[i][0] = fma2(a2n, w2n.x, acc[i][0]);
                    acc[i][1] = fma2(a2n, w2n.y, acc[i][1]);
                }
            }
        }

        #pragma unroll
        for (int i = 0; i < 4; i++) {
            int row = rowbase + r0 + i;
            if (row < N_NODES) {
                float2 lo = unpack2(acc[i][0]);
                float2 hi = unpack2(acc[i][1]);
                float4 o = make_float4(lo.x, lo.y, hi.x, hi.y);
                *reinterpret_cast<float4*>(out + (size_t)row * D + c0) = o;
            }
        }
    }
}

// ---------------- launch ----------------
extern "C" void kernel_launch(void* const* d_in, const int* in_sizes, int n_in,
                              void* d_out, int out_size) {
    const float* h      = (const float*)d_in[0];
    const void*  src    = d_in[1];
    const void*  dst    = d_in[2];
    const float* Wself  = (const float*)d_in[3];
    const float* Wneigh = (const float*)d_in[4];
    float*       out    = (float*)d_out;

    static bool attr_set = false;
    if (!attr_set) {
        cudaFuncSetAttribute(out_kernel,
                             cudaFuncAttributeMaxDynamicSharedMemorySize,
                             196608);
        attr_set = true;
    }

    sniff_kernel<<<1, 32>>>(src);
    zero_kernel<<<4096, 256>>>();
    edge_kernel<<<16384, 256>>>(h, src, dst);
    out_kernel<<<152, 512, 196608>>>(h, Wself, Wneigh, out);
}